// round 13
// baseline (speedup 1.0000x reference)
#include <cuda_runtime.h>
#include <cuda_bf16.h>
#include <cstdint>
#include <cstddef>

#define BATCH 8
#define CC    512
#define LL    2048
#define NGROUPS 32
#define CPG   (CC / NGROUPS)
#define GROUP_ELEMS (CPG * LL)
#define EPS   1e-5f

// ---------------------------------------------------------------------------
// Device scratch (all GEMM operands k-contiguous)
// ---------------------------------------------------------------------------
__device__ __nv_bfloat16 g_hT[(size_t)BATCH * LL * CC];   // [b][l][c]
__device__ __nv_bfloat16 g_qT[(size_t)BATCH * LL * CC];   // [b][l][c]
__device__ __nv_bfloat16 g_kT[(size_t)BATCH * LL * CC];   // [b][l][c]
__device__ __nv_bfloat16 g_v [(size_t)BATCH * CC * LL];   // [b][c][l]
__device__ __nv_bfloat16 g_aT[(size_t)BATCH * LL * CC];   // [b][l][c]
__device__ __nv_bfloat16 g_e [(size_t)BATCH * LL * LL];   // exp(scores) bf16
__device__ float         g_part[(size_t)BATCH * LL * 32]; // rowsum partials
__device__ float         g_invrs[(size_t)BATCH * LL];     // 1/rowsum
__device__ float2        g_stats[BATCH * NGROUPS];

// ---------------------------------------------------------------------------
// Helpers
// ---------------------------------------------------------------------------
__device__ __forceinline__ float warp_sum(float v) {
    #pragma unroll
    for (int o = 16; o > 0; o >>= 1) v += __shfl_xor_sync(0xffffffffu, v, o);
    return v;
}
__device__ __forceinline__ void ldsm4(uint32_t* r, const void* p) {
    uint32_t a = (uint32_t)__cvta_generic_to_shared(p);
    asm volatile("ldmatrix.sync.aligned.m8n8.x4.shared.b16 {%0,%1,%2,%3}, [%4];"
                 : "=r"(r[0]), "=r"(r[1]), "=r"(r[2]), "=r"(r[3]) : "r"(a));
}
__device__ __forceinline__ void mma16(float* d, const uint32_t* a, const uint32_t* b) {
    asm volatile(
        "mma.sync.aligned.m16n8k16.row.col.f32.bf16.bf16.f32 "
        "{%0,%1,%2,%3}, {%4,%5,%6,%7}, {%8,%9}, {%0,%1,%2,%3};\n"
        : "+f"(d[0]), "+f"(d[1]), "+f"(d[2]), "+f"(d[3])
        : "r"(a[0]), "r"(a[1]), "r"(a[2]), "r"(a[3]), "r"(b[0]), "r"(b[1]));
}
__device__ __forceinline__ uint32_t packbf2(float x, float y) {
    __nv_bfloat162 t = __floats2bfloat162_rn(x, y);
    return *(uint32_t*)&t;
}
__device__ __forceinline__ uint4 pack8(float4 a, float4 b) {
    uint4 r;
    r.x = packbf2(a.x, a.y); r.y = packbf2(a.z, a.w);
    r.z = packbf2(b.x, b.y); r.w = packbf2(b.z, b.w);
    return r;
}
__device__ __forceinline__ void cp16(void* smem_dst, const void* gmem_src) {
    uint32_t d = (uint32_t)__cvta_generic_to_shared(smem_dst);
    asm volatile("cp.async.cg.shared.global [%0], [%1], 16;" :: "r"(d), "l"(gmem_src));
}
__device__ __forceinline__ void cp_commit() {
    asm volatile("cp.async.commit_group;" ::: "memory");
}
__device__ __forceinline__ void cp_wait1() {
    asm volatile("cp.async.wait_group 1;" ::: "memory");
}

// ---------------------------------------------------------------------------
// GroupNorm pass 1 (stats)
// ---------------------------------------------------------------------------
__global__ void gn_stats(const float* __restrict__ x, float2* __restrict__ stats) {
    const int bg = blockIdx.x;
    const int b  = bg / NGROUPS;
    const int g  = bg % NGROUPS;
    const size_t base = ((size_t)b * CC + (size_t)g * CPG) * LL;
    const float* xp = x + base;

    float s = 0.f, s2 = 0.f;
    for (int i = threadIdx.x; i < GROUP_ELEMS; i += blockDim.x) {
        float v = xp[i];
        s += v; s2 += v * v;
    }
    __shared__ float red1[16], red2[16];
    s = warp_sum(s); s2 = warp_sum(s2);
    const int lane = threadIdx.x & 31, wid = threadIdx.x >> 5;
    if (lane == 0) { red1[wid] = s; red2[wid] = s2; }
    __syncthreads();
    if (threadIdx.x == 0) {
        float t = 0.f, t2 = 0.f;
        #pragma unroll
        for (int i = 0; i < 16; i++) { t += red1[i]; t2 += red2[i]; }
        float mean = t * (1.0f / GROUP_ELEMS);
        float var  = t2 * (1.0f / GROUP_ELEMS) - mean * mean;
        stats[bg] = make_float2(mean, rsqrtf(var + EPS));
    }
}

// ---------------------------------------------------------------------------
// GroupNorm pass 2: normalize + transpose + bf16 -> hT[b][l][c]
// ---------------------------------------------------------------------------
__global__ void gn_norm_t(const float* __restrict__ x,
                          const float2* __restrict__ stats,
                          const float* __restrict__ gamma,
                          const float* __restrict__ beta,
                          __nv_bfloat16* __restrict__ hT) {
    const int b = blockIdx.z;
    const int l0 = blockIdx.x * 32;
    const int c0 = blockIdx.y * 64;
    const int tx = threadIdx.x & 31, ty = threadIdx.x >> 5;
    __shared__ float tile[64][33];

    const float* xb = x + (size_t)b * CC * LL;
    #pragma unroll
    for (int i = 0; i < 8; i++) {
        int c = c0 + i * 8 + ty;
        float2 st = stats[b * NGROUPS + (c >> 4)];
        float gm = gamma[c], bt = beta[c];
        float xv = xb[(size_t)c * LL + l0 + tx];
        tile[c - c0][tx] = (xv - st.x) * st.y * gm + bt;
    }
    __syncthreads();
    __nv_bfloat16* ht = hT + (size_t)b * LL * CC;
    #pragma unroll
    for (int i = 0; i < 4; i++) {
        int l = i * 8 + ty;
        __nv_bfloat162 o;
        o.x = __float2bfloat16_rn(tile[tx * 2][l]);
        o.y = __float2bfloat16_rn(tile[tx * 2 + 1][l]);
        *(__nv_bfloat162*)(ht + (size_t)(l0 + l) * CC + c0 + tx * 2) = o;
    }
}

// ---------------------------------------------------------------------------
// bf16 mma.sync GEMM.  4 warps (2x2), CTA tile 128x128 x BK=64,
// warp tile 64x64.  3-stage cp.async, ONE barrier per k-tile.
// 2 CTAs/SM, prefetch 2 tiles ahead of compute.
//   out[b,m,n] = sum_k A[m,k] * B[n,k]  (+ epilogue)
// EPI: 1 +bias[m] ; 2 +bias[m]+X, fp32 out ; 3 exp(v*scale) + rowsum partials
//      4 +bias[n] ; 5 *aux[m] (inv rowsum)
// Merged mode: if Bg2 != nullptr, z >= gridDim.z/2 uses (Bg2, Og2, bias2).
// ---------------------------------------------------------------------------
#define BKK 64
#define SROW 72        // 64 + 8 pad (144B rows: 16B aligned, ldmatrix conflict-free)
#define STG_ELEM (128 * SROW)
#define NSTG 3
#define SM_TOTAL (2 * NSTG * STG_ELEM * 2)   // 3 stages x (A+B) bf16 = 110592 B

template<int EPI, bool A_F32, bool B_F32, bool OUT_BF16>
__global__ __launch_bounds__(128, 2)
void gemm_cp(const void* __restrict__ Ag, int lda, size_t strA,
             const void* __restrict__ Bg, int ldb, size_t strB,
             void* __restrict__ Og, int ldo, size_t strO,
             int K, const float* __restrict__ bias,
             const float* __restrict__ X, size_t strX,
             float scale, float* __restrict__ aux,
             const void* __restrict__ Bg2, void* __restrict__ Og2,
             const float* __restrict__ bias2) {
    extern __shared__ __align__(16) __nv_bfloat16 smem[];
    __nv_bfloat16* smA = smem;                    // NSTG stages
    __nv_bfloat16* smB = smem + NSTG * STG_ELEM;  // NSTG stages

    const int tid = threadIdx.x, lane = tid & 31, warp = tid >> 5;   // warp 0..3
    const int wm = warp >> 1, wn = warp & 1;                          // 2x2
    const int g = lane >> 2, tig = lane & 3;
    const int mBase = blockIdx.y * 128, nBase = blockIdx.x * 128;

    // merged q/k dispatch
    int zz = blockIdx.z;
    const void* Bu = Bg; void* Ou = Og; const float* biasu = bias;
    if (Bg2 != nullptr) {
        const int half = (int)(gridDim.z >> 1);
        if (zz >= half) { Bu = Bg2; Ou = Og2; biasu = bias2; zz -= half; }
    }
    const int z = zz;

    const int nk = K / BKK;

    auto issue_stage = [&](int kt) {
        if (kt < nk) {
            const int buf = kt % NSTG;
            const int k0 = kt * BKK;
            __nv_bfloat16* sA = smA + buf * STG_ELEM;
            __nv_bfloat16* sB = smB + buf * STG_ELEM;
            #pragma unroll
            for (int it = 0; it < 8; it++) {
                const int s = tid + it * 128;
                const int row = s >> 3;
                const int col8 = (s & 7) * 8;
                if constexpr (A_F32) {
                    const float* p = (const float*)Ag + strA * z
                                   + (size_t)(mBase + row) * lda + k0 + col8;
                    *(uint4*)(sA + row * SROW + col8) =
                        pack8(*(const float4*)p, *(const float4*)(p + 4));
                } else {
                    const __nv_bfloat16* p = (const __nv_bfloat16*)Ag + strA * z
                                           + (size_t)(mBase + row) * lda + k0 + col8;
                    cp16(sA + row * SROW + col8, p);
                }
                if constexpr (B_F32) {
                    const float* p = (const float*)Bu + strB * z
                                   + (size_t)(nBase + row) * ldb + k0 + col8;
                    *(uint4*)(sB + row * SROW + col8) =
                        pack8(*(const float4*)p, *(const float4*)(p + 4));
                } else {
                    const __nv_bfloat16* p = (const __nv_bfloat16*)Bu + strB * z
                                           + (size_t)(nBase + row) * ldb + k0 + col8;
                    cp16(sB + row * SROW + col8, p);
                }
            }
        }
        cp_commit();
    };

    float acc[4][8][4];
    #pragma unroll
    for (int i = 0; i < 4; i++)
        #pragma unroll
        for (int j = 0; j < 8; j++)
            #pragma unroll
            for (int r = 0; r < 4; r++) acc[i][j][r] = 0.f;

    issue_stage(0);
    issue_stage(1);

    for (int kt = 0; kt < nk; kt++) {
        const int buf = kt % NSTG;
        const __nv_bfloat16* sA = smA + buf * STG_ELEM;
        const __nv_bfloat16* sB = smB + buf * STG_ELEM;

        cp_wait1();            // stage kt resident (kt+1 may be in flight)
        __syncthreads();       // all warps done with stage kt-1 reads

        issue_stage(kt + 2);   // fill (kt-1)%3 — its readers passed the barrier

        #pragma unroll
        for (int ks = 0; ks < 4; ks++) {
            uint32_t af[4][4], bf[8][2];
            #pragma unroll
            for (int mt = 0; mt < 4; mt++) {
                const __nv_bfloat16* p = &sA[(wm * 64 + mt * 16 + (lane & 15)) * SROW
                                             + ks * 16 + ((lane >> 4) << 3)];
                ldsm4(af[mt], p);
            }
            #pragma unroll
            for (int np = 0; np < 4; np++) {
                const __nv_bfloat16* p = &sB[(wn * 64 + np * 16 + (lane & 7) + ((lane >> 4) << 3)) * SROW
                                             + ks * 16 + (((lane >> 3) & 1) << 3)];
                uint32_t t[4];
                ldsm4(t, p);
                bf[np * 2][0] = t[0]; bf[np * 2][1] = t[1];
                bf[np * 2 + 1][0] = t[2]; bf[np * 2 + 1][1] = t[3];
            }
            #pragma unroll
            for (int mt = 0; mt < 4; mt++)
                #pragma unroll
                for (int nt = 0; nt < 8; nt++)
                    mma16(acc[mt][nt], af[mt], bf[nt]);
        }
    }

    __syncthreads();

    // ---- epilogue ----
    float bn0[8], bn1[8];
    if (EPI == 4) {
        #pragma unroll
        for (int nt = 0; nt < 8; nt++) {
            int col = nBase + wn * 64 + nt * 8 + tig * 2;
            bn0[nt] = biasu[col]; bn1[nt] = biasu[col + 1];
        }
    }
    #pragma unroll
    for (int mt = 0; mt < 4; mt++) {
        #pragma unroll
        for (int half = 0; half < 2; half++) {
            const int row = mBase + wm * 64 + mt * 16 + g + half * 8;
            float bm = (EPI == 1 || EPI == 2) ? biasu[row] : 0.f;
            float rsmul = (EPI == 5) ? aux[(size_t)z * LL + row] : 0.f;
            float rsum = 0.f;
            #pragma unroll
            for (int nt = 0; nt < 8; nt++) {
                const int col = nBase + wn * 64 + nt * 8 + tig * 2;
                float v0 = acc[mt][nt][half * 2 + 0];
                float v1 = acc[mt][nt][half * 2 + 1];
                if (EPI == 1 || EPI == 2) { v0 += bm; v1 += bm; }
                if (EPI == 4) { v0 += bn0[nt]; v1 += bn1[nt]; }
                if (EPI == 5) { v0 *= rsmul; v1 *= rsmul; }
                if (EPI == 2) {
                    const float* xr = X + strX * z + (size_t)row * ldo + col;
                    v0 += xr[0]; v1 += xr[1];
                }
                if (EPI == 3) {
                    v0 = __expf(v0 * scale);
                    v1 = __expf(v1 * scale);
                    __nv_bfloat162 st = __floats2bfloat162_rn(v0, v1);
                    *(__nv_bfloat162*)((__nv_bfloat16*)Ou + strO * z
                                       + (size_t)row * ldo + col) = st;
                    rsum += __bfloat162float(st.x) + __bfloat162float(st.y);
                } else if constexpr (OUT_BF16) {
                    __nv_bfloat162 st = __floats2bfloat162_rn(v0, v1);
                    *(__nv_bfloat162*)((__nv_bfloat16*)Ou + strO * z
                                       + (size_t)row * ldo + col) = st;
                } else {
                    float2 st = { v0, v1 };
                    *(float2*)((float*)Ou + strO * z + (size_t)row * ldo + col) = st;
                }
            }
            if (EPI == 3) {
                rsum += __shfl_xor_sync(0xffffffffu, rsum, 1);
                rsum += __shfl_xor_sync(0xffffffffu, rsum, 2);
                if (tig == 0)
                    aux[((size_t)z * LL + row) * 32 + blockIdx.x * 2 + wn] = rsum;
            }
        }
    }
}

// ---------------------------------------------------------------------------
// Rowsum reduce: 32 partials per row -> 1/rowsum
// ---------------------------------------------------------------------------
__global__ __launch_bounds__(256)
void rs_reduce(const float* __restrict__ part, float* __restrict__ invrs) {
    const int row = blockIdx.x * 8 + (threadIdx.x >> 5);
    const int lane = threadIdx.x & 31;
    float s = part[(size_t)row * 32 + lane];
    s = warp_sum(s);
    if (lane == 0) invrs[row] = 1.0f / s;
}

// ---------------------------------------------------------------------------
// Launch
// ---------------------------------------------------------------------------
extern "C" void kernel_launch(void* const* d_in, const int* in_sizes, int n_in,
                              void* d_out, int out_size) {
    const float* x        = (const float*)d_in[0];
    const float* gn_gamma = (const float*)d_in[1];
    const float* gn_beta  = (const float*)d_in[2];
    const float* Wq = (const float*)d_in[3];
    const float* bq = (const float*)d_in[4];
    const float* Wk = (const float*)d_in[5];
    const float* bk = (const float*)d_in[6];
    const float* Wv = (const float*)d_in[7];
    const float* bv = (const float*)d_in[8];
    const float* Wo = (const float*)d_in[9];
    const float* bo = (const float*)d_in[10];
    float* out = (float*)d_out;

    __nv_bfloat16 *hT, *qT, *kT, *v, *aT, *e;
    float *part, *invrs; float2* stats;
    cudaGetSymbolAddress((void**)&hT, g_hT);
    cudaGetSymbolAddress((void**)&qT, g_qT);
    cudaGetSymbolAddress((void**)&kT, g_kT);
    cudaGetSymbolAddress((void**)&v,  g_v);
    cudaGetSymbolAddress((void**)&aT, g_aT);
    cudaGetSymbolAddress((void**)&e,  g_e);
    cudaGetSymbolAddress((void**)&part, g_part);
    cudaGetSymbolAddress((void**)&invrs, g_invrs);
    cudaGetSymbolAddress((void**)&stats, g_stats);

    const size_t CL  = (size_t)CC * LL;
    const size_t LLs = (size_t)LL * LL;
    const float scale = 0.044194173824159216f;   // 1/sqrt(512)

    cudaFuncSetAttribute(gemm_cp<4, false, true,  true>,
                         cudaFuncAttributeMaxDynamicSharedMemorySize, SM_TOTAL);
    cudaFuncSetAttribute(gemm_cp<1, true,  false, true>,
                         cudaFuncAttributeMaxDynamicSharedMemorySize, SM_TOTAL);
    cudaFuncSetAttribute(gemm_cp<3, false, false, true>,
                         cudaFuncAttributeMaxDynamicSharedMemorySize, SM_TOTAL);
    cudaFuncSetAttribute(gemm_cp<5, false, false, true>,
                         cudaFuncAttributeMaxDynamicSharedMemorySize, SM_TOTAL);
    cudaFuncSetAttribute(gemm_cp<2, true,  false, false>,
                         cudaFuncAttributeMaxDynamicSharedMemorySize, SM_TOTAL);

    // 1. GroupNorm
    gn_stats<<<BATCH * NGROUPS, 512>>>(x, stats);
    gn_norm_t<<<dim3(LL / 32, CC / 64, BATCH), 256>>>(x, stats, gn_gamma, gn_beta, hT);

    // 2. merged q & k:  qT/kT[l][o] = hT @ W^T + b   (M=L, N=C, K=C), z=16
    dim3 gQK(CC / 128, LL / 128, 2 * BATCH);
    gemm_cp<4, false, true, true><<<gQK, 128, SM_TOTAL>>>(
        hT, CC, CL, Wq, CC, 0, qT, CC, CL, CC, bq, nullptr, 0, 0.f, nullptr,
        Wk, kT, bk);
    //    v[c][l] = Wv @ h + bv   (M=C, N=L, K=C)
    dim3 gV(LL / 128, CC / 128, BATCH);
    gemm_cp<1, true, false, true><<<gV, 128, SM_TOTAL>>>(
        Wv, CC, 0, hT, CC, CL, v, LL, CL, CC, bv, nullptr, 0, 0.f, nullptr,
        nullptr, nullptr, nullptr);

    // 3. e[i][j] = exp(scale * qT@kT^T), + rowsum partials  (M=N=L, K=C)
    dim3 gS(LL / 128, LL / 128, BATCH);
    gemm_cp<3, false, false, true><<<gS, 128, SM_TOTAL>>>(
        qT, CC, CL, kT, CC, CL, e, LL, LLs, CC, nullptr, nullptr, 0, scale, part,
        nullptr, nullptr, nullptr);

    // 4. 1/rowsum
    rs_reduce<<<BATCH * LL / 8, 256>>>(part, invrs);

    // 5. aT[i][c] = (e @ v^T) * invrs[i]   (M=L, N=C, K=L)
    dim3 gT(CC / 128, LL / 128, BATCH);
    gemm_cp<5, false, false, true><<<gT, 128, SM_TOTAL>>>(
        e, LL, LLs, v, LL, CL, aT, CC, CL, LL, nullptr, nullptr, 0, 0.f, invrs,
        nullptr, nullptr, nullptr);

    // 6. out[o][l] = x + Wo @ aT^T + bo   (M=C, N=L, K=C)
    gemm_cp<2, true, false, false><<<gV, 128, SM_TOTAL>>>(
        Wo, CC, 0, aT, CC, CL, out, LL, CL, CC, bo, x, CL, 0.f, nullptr,
        nullptr, nullptr, nullptr);
}

// round 14
// speedup vs baseline: 1.0529x; 1.0529x over previous
#include <cuda_runtime.h>
#include <cuda_bf16.h>
#include <cstdint>
#include <cstddef>

#define BATCH 8
#define CC    512
#define LL    2048
#define NGROUPS 32
#define CPG   (CC / NGROUPS)
#define GROUP_ELEMS (CPG * LL)
#define EPS   1e-5f

// ---------------------------------------------------------------------------
// Device scratch (all GEMM operands k-contiguous)
// ---------------------------------------------------------------------------
__device__ __nv_bfloat16 g_hT[(size_t)BATCH * LL * CC];   // [b][l][c]
__device__ __nv_bfloat16 g_qT[(size_t)BATCH * LL * CC];   // [b][l][c]
__device__ __nv_bfloat16 g_kT[(size_t)BATCH * LL * CC];   // [b][l][c]
__device__ __nv_bfloat16 g_v [(size_t)BATCH * CC * LL];   // [b][c][l]
__device__ __nv_bfloat16 g_aT[(size_t)BATCH * LL * CC];   // [b][l][c]
__device__ __nv_bfloat16 g_e [(size_t)BATCH * LL * LL];   // exp(scores) bf16
__device__ float         g_part[(size_t)BATCH * LL * 32]; // rowsum partials
__device__ float2        g_stats[BATCH * NGROUPS];

// ---------------------------------------------------------------------------
// Helpers
// ---------------------------------------------------------------------------
__device__ __forceinline__ float warp_sum(float v) {
    #pragma unroll
    for (int o = 16; o > 0; o >>= 1) v += __shfl_xor_sync(0xffffffffu, v, o);
    return v;
}
__device__ __forceinline__ void ldsm4(uint32_t* r, const void* p) {
    uint32_t a = (uint32_t)__cvta_generic_to_shared(p);
    asm volatile("ldmatrix.sync.aligned.m8n8.x4.shared.b16 {%0,%1,%2,%3}, [%4];"
                 : "=r"(r[0]), "=r"(r[1]), "=r"(r[2]), "=r"(r[3]) : "r"(a));
}
__device__ __forceinline__ void mma16(float* d, const uint32_t* a, const uint32_t* b) {
    asm volatile(
        "mma.sync.aligned.m16n8k16.row.col.f32.bf16.bf16.f32 "
        "{%0,%1,%2,%3}, {%4,%5,%6,%7}, {%8,%9}, {%0,%1,%2,%3};\n"
        : "+f"(d[0]), "+f"(d[1]), "+f"(d[2]), "+f"(d[3])
        : "r"(a[0]), "r"(a[1]), "r"(a[2]), "r"(a[3]), "r"(b[0]), "r"(b[1]));
}
__device__ __forceinline__ uint32_t packbf2(float x, float y) {
    __nv_bfloat162 t = __floats2bfloat162_rn(x, y);
    return *(uint32_t*)&t;
}
__device__ __forceinline__ uint4 pack8(float4 a, float4 b) {
    uint4 r;
    r.x = packbf2(a.x, a.y); r.y = packbf2(a.z, a.w);
    r.z = packbf2(b.x, b.y); r.w = packbf2(b.z, b.w);
    return r;
}
__device__ __forceinline__ void cp16(void* smem_dst, const void* gmem_src) {
    uint32_t d = (uint32_t)__cvta_generic_to_shared(smem_dst);
    asm volatile("cp.async.cg.shared.global [%0], [%1], 16;" :: "r"(d), "l"(gmem_src));
}
__device__ __forceinline__ void cp_commit() {
    asm volatile("cp.async.commit_group;" ::: "memory");
}
__device__ __forceinline__ void cp_wait1() {
    asm volatile("cp.async.wait_group 1;" ::: "memory");
}

// ---------------------------------------------------------------------------
// GroupNorm pass 1 (stats)
// ---------------------------------------------------------------------------
__global__ void gn_stats(const float* __restrict__ x, float2* __restrict__ stats) {
    const int bg = blockIdx.x;
    const int b  = bg / NGROUPS;
    const int g  = bg % NGROUPS;
    const size_t base = ((size_t)b * CC + (size_t)g * CPG) * LL;
    const float* xp = x + base;

    float s = 0.f, s2 = 0.f;
    for (int i = threadIdx.x; i < GROUP_ELEMS; i += blockDim.x) {
        float v = xp[i];
        s += v; s2 += v * v;
    }
    __shared__ float red1[16], red2[16];
    s = warp_sum(s); s2 = warp_sum(s2);
    const int lane = threadIdx.x & 31, wid = threadIdx.x >> 5;
    if (lane == 0) { red1[wid] = s; red2[wid] = s2; }
    __syncthreads();
    if (threadIdx.x == 0) {
        float t = 0.f, t2 = 0.f;
        #pragma unroll
        for (int i = 0; i < 16; i++) { t += red1[i]; t2 += red2[i]; }
        float mean = t * (1.0f / GROUP_ELEMS);
        float var  = t2 * (1.0f / GROUP_ELEMS) - mean * mean;
        stats[bg] = make_float2(mean, rsqrtf(var + EPS));
    }
}

// ---------------------------------------------------------------------------
// GroupNorm pass 2: normalize + transpose + bf16 -> hT[b][l][c]
// ---------------------------------------------------------------------------
__global__ void gn_norm_t(const float* __restrict__ x,
                          const float2* __restrict__ stats,
                          const float* __restrict__ gamma,
                          const float* __restrict__ beta,
                          __nv_bfloat16* __restrict__ hT) {
    const int b = blockIdx.z;
    const int l0 = blockIdx.x * 32;
    const int c0 = blockIdx.y * 64;
    const int tx = threadIdx.x & 31, ty = threadIdx.x >> 5;
    __shared__ float tile[64][33];

    const float* xb = x + (size_t)b * CC * LL;
    #pragma unroll
    for (int i = 0; i < 8; i++) {
        int c = c0 + i * 8 + ty;
        float2 st = stats[b * NGROUPS + (c >> 4)];
        float gm = gamma[c], bt = beta[c];
        float xv = xb[(size_t)c * LL + l0 + tx];
        tile[c - c0][tx] = (xv - st.x) * st.y * gm + bt;
    }
    __syncthreads();
    __nv_bfloat16* ht = hT + (size_t)b * LL * CC;
    #pragma unroll
    for (int i = 0; i < 4; i++) {
        int l = i * 8 + ty;
        __nv_bfloat162 o;
        o.x = __float2bfloat16_rn(tile[tx * 2][l]);
        o.y = __float2bfloat16_rn(tile[tx * 2 + 1][l]);
        *(__nv_bfloat162*)(ht + (size_t)(l0 + l) * CC + c0 + tx * 2) = o;
    }
}

// ---------------------------------------------------------------------------
// R10 GEMM engine as a device body.  4 warps (2x2), CTA tile 128x128 x BK=64,
// warp tile 64x64, 2-stage cp.async, two barriers per k-tile.  2 CTAs/SM.
//   out[m,n] = sum_k A[m,k] * B[n,k]  (+ epilogue)
// EPI: 1 +bias[m] ; 2 +bias[m]+X, fp32 out ; 3 exp(v*scale) + rowsum partials
//      4 +bias[n] ; 5 * (1/rowsum[m]) reduced inline from aux partials
// ---------------------------------------------------------------------------
#define BKK 64
#define SROW 72        // 64 + 8 pad (144B rows: 16B aligned, ldmatrix conflict-free)
#define STG_ELEM (128 * SROW)
#define SM_TOTAL (4 * STG_ELEM * 2)   // 2 stages x (A+B) bf16 = 73728 B

template<int EPI, bool A_F32, bool B_F32, bool OUT_BF16>
__device__ __forceinline__
void gemm_body(__nv_bfloat16* smem, int bx, int by, int z,
               const void* __restrict__ Ag, int lda, size_t strA,
               const void* __restrict__ Bg, int ldb, size_t strB,
               void* __restrict__ Og, int ldo, size_t strO,
               int K, const float* __restrict__ bias,
               const float* __restrict__ X, size_t strX,
               float scale, float* __restrict__ aux) {
    __nv_bfloat16* smA = smem;                 // 2 stages
    __nv_bfloat16* smB = smem + 2 * STG_ELEM;  // 2 stages

    const int tid = threadIdx.x, lane = tid & 31, warp = tid >> 5;   // warp 0..3
    const int wm = warp >> 1, wn = warp & 1;                          // 2x2
    const int g = lane >> 2, tig = lane & 3;
    const int mBase = by * 128, nBase = bx * 128;

    const int nk = K / BKK;

    auto issue_stage = [&](int kt) {
        if (kt < nk) {
            const int buf = kt & 1;
            const int k0 = kt * BKK;
            __nv_bfloat16* sA = smA + buf * STG_ELEM;
            __nv_bfloat16* sB = smB + buf * STG_ELEM;
            #pragma unroll
            for (int it = 0; it < 8; it++) {
                const int s = tid + it * 128;
                const int row = s >> 3;
                const int col8 = (s & 7) * 8;
                if constexpr (A_F32) {
                    const float* p = (const float*)Ag + strA * z
                                   + (size_t)(mBase + row) * lda + k0 + col8;
                    *(uint4*)(sA + row * SROW + col8) =
                        pack8(*(const float4*)p, *(const float4*)(p + 4));
                } else {
                    const __nv_bfloat16* p = (const __nv_bfloat16*)Ag + strA * z
                                           + (size_t)(mBase + row) * lda + k0 + col8;
                    cp16(sA + row * SROW + col8, p);
                }
                if constexpr (B_F32) {
                    const float* p = (const float*)Bg + strB * z
                                   + (size_t)(nBase + row) * ldb + k0 + col8;
                    *(uint4*)(sB + row * SROW + col8) =
                        pack8(*(const float4*)p, *(const float4*)(p + 4));
                } else {
                    const __nv_bfloat16* p = (const __nv_bfloat16*)Bg + strB * z
                                           + (size_t)(nBase + row) * ldb + k0 + col8;
                    cp16(sB + row * SROW + col8, p);
                }
            }
        }
        cp_commit();
    };

    float acc[4][8][4];
    #pragma unroll
    for (int i = 0; i < 4; i++)
        #pragma unroll
        for (int j = 0; j < 8; j++)
            #pragma unroll
            for (int r = 0; r < 4; r++) acc[i][j][r] = 0.f;

    issue_stage(0);
    issue_stage(1);

    for (int kt = 0; kt < nk; kt++) {
        const int buf = kt & 1;
        const __nv_bfloat16* sA = smA + buf * STG_ELEM;
        const __nv_bfloat16* sB = smB + buf * STG_ELEM;

        cp_wait1();            // stage kt resident
        __syncthreads();

        #pragma unroll
        for (int ks = 0; ks < 4; ks++) {
            uint32_t af[4][4], bf[8][2];
            #pragma unroll
            for (int mt = 0; mt < 4; mt++) {
                const __nv_bfloat16* p = &sA[(wm * 64 + mt * 16 + (lane & 15)) * SROW
                                             + ks * 16 + ((lane >> 4) << 3)];
                ldsm4(af[mt], p);
            }
            #pragma unroll
            for (int np = 0; np < 4; np++) {
                const __nv_bfloat16* p = &sB[(wn * 64 + np * 16 + (lane & 7) + ((lane >> 4) << 3)) * SROW
                                             + ks * 16 + (((lane >> 3) & 1) << 3)];
                uint32_t t[4];
                ldsm4(t, p);
                bf[np * 2][0] = t[0]; bf[np * 2][1] = t[1];
                bf[np * 2 + 1][0] = t[2]; bf[np * 2 + 1][1] = t[3];
            }
            #pragma unroll
            for (int mt = 0; mt < 4; mt++)
                #pragma unroll
                for (int nt = 0; nt < 8; nt++)
                    mma16(acc[mt][nt], af[mt], bf[nt]);
        }

        __syncthreads();       // all warps finished reading buf
        issue_stage(kt + 2);   // refill it
    }

    // ---- epilogue ----
    float bn0[8], bn1[8];
    if (EPI == 4) {
        #pragma unroll
        for (int nt = 0; nt < 8; nt++) {
            int col = nBase + wn * 64 + nt * 8 + tig * 2;
            bn0[nt] = bias[col]; bn1[nt] = bias[col + 1];
        }
    }
    #pragma unroll
    for (int mt = 0; mt < 4; mt++) {
        #pragma unroll
        for (int half = 0; half < 2; half++) {
            const int row = mBase + wm * 64 + mt * 16 + g + half * 8;
            float bm = (EPI == 1 || EPI == 2) ? bias[row] : 0.f;
            float rsmul = 0.f;
            if (EPI == 5) {
                // inline rowsum reduce: 32 partials, quad-cooperative
                const float* pp = aux + ((size_t)z * LL + row) * 32 + tig * 8;
                float s0 = (pp[0] + pp[1]) + (pp[2] + pp[3]);
                float s1 = (pp[4] + pp[5]) + (pp[6] + pp[7]);
                float s = s0 + s1;
                s += __shfl_xor_sync(0xffffffffu, s, 1);
                s += __shfl_xor_sync(0xffffffffu, s, 2);
                rsmul = 1.0f / s;
            }
            float rsum = 0.f;
            #pragma unroll
            for (int nt = 0; nt < 8; nt++) {
                const int col = nBase + wn * 64 + nt * 8 + tig * 2;
                float v0 = acc[mt][nt][half * 2 + 0];
                float v1 = acc[mt][nt][half * 2 + 1];
                if (EPI == 1 || EPI == 2) { v0 += bm; v1 += bm; }
                if (EPI == 4) { v0 += bn0[nt]; v1 += bn1[nt]; }
                if (EPI == 5) { v0 *= rsmul; v1 *= rsmul; }
                if (EPI == 2) {
                    const float* xr = X + strX * z + (size_t)row * ldo + col;
                    v0 += xr[0]; v1 += xr[1];
                }
                if (EPI == 3) {
                    v0 = __expf(v0 * scale);
                    v1 = __expf(v1 * scale);
                    __nv_bfloat162 st = __floats2bfloat162_rn(v0, v1);
                    *(__nv_bfloat162*)((__nv_bfloat16*)Og + strO * z
                                       + (size_t)row * ldo + col) = st;
                    rsum += __bfloat162float(st.x) + __bfloat162float(st.y);
                } else if constexpr (OUT_BF16) {
                    __nv_bfloat162 st = __floats2bfloat162_rn(v0, v1);
                    *(__nv_bfloat162*)((__nv_bfloat16*)Og + strO * z
                                       + (size_t)row * ldo + col) = st;
                } else {
                    float2 st = { v0, v1 };
                    *(float2*)((float*)Og + strO * z + (size_t)row * ldo + col) = st;
                }
            }
            if (EPI == 3) {
                rsum += __shfl_xor_sync(0xffffffffu, rsum, 1);
                rsum += __shfl_xor_sync(0xffffffffu, rsum, 2);
                if (tig == 0)
                    aux[((size_t)z * LL + row) * 32 + bx * 2 + wn] = rsum;
            }
        }
    }
}

// ---------------------------------------------------------------------------
// Kernel wrappers
// ---------------------------------------------------------------------------
template<int EPI, bool A_F32, bool B_F32, bool OUT_BF16>
__global__ __launch_bounds__(128, 2)
void gemm_k(const void* __restrict__ Ag, int lda, size_t strA,
            const void* __restrict__ Bg, int ldb, size_t strB,
            void* __restrict__ Og, int ldo, size_t strO,
            int K, const float* __restrict__ bias,
            const float* __restrict__ X, size_t strX,
            float scale, float* __restrict__ aux) {
    extern __shared__ __align__(16) __nv_bfloat16 smem[];
    gemm_body<EPI, A_F32, B_F32, OUT_BF16>(
        smem, blockIdx.x, blockIdx.y, blockIdx.z,
        Ag, lda, strA, Bg, ldb, strB, Og, ldo, strO,
        K, bias, X, strX, scale, aux);
}

// Merged q/k/V projections in one 1D launch.
//  blocks [0, 1024):  qk — bx=bid&3, by=(bid>>2)&15, zz=bid>>6 (0..15)
//                     zz<8 -> Wq/qT/bq batch zz ; else Wk/kT/bk batch zz-8
//  blocks [1024, 1536): V — t=bid-1024: bx=t&15, by=(t>>4)&3, z=t>>6
#define QK_BLOCKS 1024
#define QKV_BLOCKS 1536

__global__ __launch_bounds__(128, 2)
void qkv_k(const __nv_bfloat16* __restrict__ hT,
           const float* __restrict__ Wq, const float* __restrict__ bq,
           __nv_bfloat16* __restrict__ qT,
           const float* __restrict__ Wk, const float* __restrict__ bk,
           __nv_bfloat16* __restrict__ kT,
           const float* __restrict__ Wv, const float* __restrict__ bv,
           __nv_bfloat16* __restrict__ v) {
    extern __shared__ __align__(16) __nv_bfloat16 smem[];
    const size_t CL = (size_t)CC * LL;
    const int bid = blockIdx.x;
    if (bid < QK_BLOCKS) {
        const int bx = bid & 3;
        const int by = (bid >> 2) & 15;
        const int zz = bid >> 6;
        const float* W = (zz < 8) ? Wq : Wk;
        const float* b = (zz < 8) ? bq : bk;
        __nv_bfloat16* O = (zz < 8) ? qT : kT;
        const int z = (zz < 8) ? zz : zz - 8;
        // qT/kT[l][o] = hT @ W^T + b[n]   (M=L, N=C, K=C)
        gemm_body<4, false, true, true>(
            smem, bx, by, z,
            hT, CC, CL, W, CC, 0, O, CC, CL, CC, b, nullptr, 0, 0.f, nullptr);
    } else {
        const int t = bid - QK_BLOCKS;
        const int bx = t & 15;
        const int by = (t >> 4) & 3;
        const int z = t >> 6;
        // v[c][l] = Wv @ h + bv[m]   (M=C, N=L, K=C)
        gemm_body<1, true, false, true>(
            smem, bx, by, z,
            Wv, CC, 0, hT, CC, CL, v, LL, CL, CC, bv, nullptr, 0, 0.f, nullptr);
    }
}

// ---------------------------------------------------------------------------
// Launch
// ---------------------------------------------------------------------------
extern "C" void kernel_launch(void* const* d_in, const int* in_sizes, int n_in,
                              void* d_out, int out_size) {
    const float* x        = (const float*)d_in[0];
    const float* gn_gamma = (const float*)d_in[1];
    const float* gn_beta  = (const float*)d_in[2];
    const float* Wq = (const float*)d_in[3];
    const float* bq = (const float*)d_in[4];
    const float* Wk = (const float*)d_in[5];
    const float* bk = (const float*)d_in[6];
    const float* Wv = (const float*)d_in[7];
    const float* bv = (const float*)d_in[8];
    const float* Wo = (const float*)d_in[9];
    const float* bo = (const float*)d_in[10];
    float* out = (float*)d_out;

    __nv_bfloat16 *hT, *qT, *kT, *v, *aT, *e;
    float *part; float2* stats;
    cudaGetSymbolAddress((void**)&hT, g_hT);
    cudaGetSymbolAddress((void**)&qT, g_qT);
    cudaGetSymbolAddress((void**)&kT, g_kT);
    cudaGetSymbolAddress((void**)&v,  g_v);
    cudaGetSymbolAddress((void**)&aT, g_aT);
    cudaGetSymbolAddress((void**)&e,  g_e);
    cudaGetSymbolAddress((void**)&part, g_part);
    cudaGetSymbolAddress((void**)&stats, g_stats);

    const size_t CL  = (size_t)CC * LL;
    const size_t LLs = (size_t)LL * LL;
    const float scale = 0.044194173824159216f;   // 1/sqrt(512)

    cudaFuncSetAttribute(qkv_k,
                         cudaFuncAttributeMaxDynamicSharedMemorySize, SM_TOTAL);
    cudaFuncSetAttribute(gemm_k<3, false, false, true>,
                         cudaFuncAttributeMaxDynamicSharedMemorySize, SM_TOTAL);
    cudaFuncSetAttribute(gemm_k<5, false, false, true>,
                         cudaFuncAttributeMaxDynamicSharedMemorySize, SM_TOTAL);
    cudaFuncSetAttribute(gemm_k<2, true,  false, false>,
                         cudaFuncAttributeMaxDynamicSharedMemorySize, SM_TOTAL);

    // 1. GroupNorm
    gn_stats<<<BATCH * NGROUPS, 512>>>(x, stats);
    gn_norm_t<<<dim3(LL / 32, CC / 64, BATCH), 256>>>(x, stats, gn_gamma, gn_beta, hT);

    // 2. merged q/k/V projections (one 1D launch, 1536 blocks)
    qkv_k<<<QKV_BLOCKS, 128, SM_TOTAL>>>(hT, Wq, bq, qT, Wk, bk, kT, Wv, bv, v);

    // 3. e[i][j] = exp(scale * qT@kT^T), + rowsum partials  (M=N=L, K=C)
    dim3 gS(LL / 128, LL / 128, BATCH);
    gemm_k<3, false, false, true><<<gS, 128, SM_TOTAL>>>(
        qT, CC, CL, kT, CC, CL, e, LL, LLs, CC, nullptr, nullptr, 0, scale, part);

    // 4. aT[i][c] = (e @ v^T) * (1/rowsum[i], reduced inline)  (M=L, N=C, K=L)
    dim3 gT(CC / 128, LL / 128, BATCH);
    gemm_k<5, false, false, true><<<gT, 128, SM_TOTAL>>>(
        e, LL, LLs, v, LL, CL, aT, CC, CL, LL, nullptr, nullptr, 0, 0.f, part);

    // 5. out[o][l] = x + Wo @ aT^T + bo   (M=C, N=L, K=C)
    dim3 gV(LL / 128, CC / 128, BATCH);
    gemm_k<2, true, false, false><<<gV, 128, SM_TOTAL>>>(
        Wo, CC, 0, aT, CC, CL, out, LL, CL, CC, bo, x, CL, 0.f, part);
}

// round 15
// speedup vs baseline: 1.1175x; 1.0613x over previous
#include <cuda_runtime.h>
#include <cuda_bf16.h>
#include <cstdint>
#include <cstddef>

#define BATCH 8
#define CC    512
#define LL    2048
#define NGROUPS 32
#define CPG   (CC / NGROUPS)
#define GROUP_ELEMS (CPG * LL)
#define EPS   1e-5f

// ---------------------------------------------------------------------------
// Device scratch (all GEMM operands k-contiguous)
// ---------------------------------------------------------------------------
__device__ __nv_bfloat16 g_hT[(size_t)BATCH * LL * CC];   // [b][l][c]
__device__ __nv_bfloat16 g_qT[(size_t)BATCH * LL * CC];   // [b][l][c]
__device__ __nv_bfloat16 g_kT[(size_t)BATCH * LL * CC];   // [b][l][c]
__device__ __nv_bfloat16 g_v [(size_t)BATCH * CC * LL];   // [b][c][l]
__device__ __nv_bfloat16 g_aT[(size_t)BATCH * LL * CC];   // [b][l][c]
__device__ __nv_bfloat16 g_e [(size_t)BATCH * LL * LL];   // exp(scores) bf16
__device__ float         g_part[(size_t)BATCH * LL * 32]; // rowsum partials
__device__ float2        g_stats[BATCH * NGROUPS];
__device__ __nv_bfloat16 g_Wbf[4 * CC * CC];              // bf16 Wq,Wk,Wv,Wo

// ---------------------------------------------------------------------------
// Helpers
// ---------------------------------------------------------------------------
__device__ __forceinline__ float warp_sum(float v) {
    #pragma unroll
    for (int o = 16; o > 0; o >>= 1) v += __shfl_xor_sync(0xffffffffu, v, o);
    return v;
}
__device__ __forceinline__ void ldsm4(uint32_t* r, const void* p) {
    uint32_t a = (uint32_t)__cvta_generic_to_shared(p);
    asm volatile("ldmatrix.sync.aligned.m8n8.x4.shared.b16 {%0,%1,%2,%3}, [%4];"
                 : "=r"(r[0]), "=r"(r[1]), "=r"(r[2]), "=r"(r[3]) : "r"(a));
}
__device__ __forceinline__ void mma16(float* d, const uint32_t* a, const uint32_t* b) {
    asm volatile(
        "mma.sync.aligned.m16n8k16.row.col.f32.bf16.bf16.f32 "
        "{%0,%1,%2,%3}, {%4,%5,%6,%7}, {%8,%9}, {%0,%1,%2,%3};\n"
        : "+f"(d[0]), "+f"(d[1]), "+f"(d[2]), "+f"(d[3])
        : "r"(a[0]), "r"(a[1]), "r"(a[2]), "r"(a[3]), "r"(b[0]), "r"(b[1]));
}
__device__ __forceinline__ uint32_t packbf2(float x, float y) {
    __nv_bfloat162 t = __floats2bfloat162_rn(x, y);
    return *(uint32_t*)&t;
}
__device__ __forceinline__ void cp16(void* smem_dst, const void* gmem_src) {
    uint32_t d = (uint32_t)__cvta_generic_to_shared(smem_dst);
    asm volatile("cp.async.cg.shared.global [%0], [%1], 16;" :: "r"(d), "l"(gmem_src));
}
__device__ __forceinline__ void cp_commit() {
    asm volatile("cp.async.commit_group;" ::: "memory");
}
__device__ __forceinline__ void cp_wait1() {
    asm volatile("cp.async.wait_group 1;" ::: "memory");
}

// ---------------------------------------------------------------------------
// Weight conversion: 4 x [CC*CC] fp32 -> bf16.  1024 blocks x 256 thr x 4 elems.
// ---------------------------------------------------------------------------
__global__ __launch_bounds__(256)
void conv_w(const float* __restrict__ Wq, const float* __restrict__ Wk,
            const float* __restrict__ Wv, const float* __restrict__ Wo,
            __nv_bfloat16* __restrict__ dst) {
    const int idx = blockIdx.x * 256 + threadIdx.x;       // 0 .. 262143
    const int mat = idx >> 16;                            // 0..3 (65536 thr/matrix)
    const int off = (idx & 65535) * 4;
    const float* src = (mat == 0) ? Wq : (mat == 1) ? Wk : (mat == 2) ? Wv : Wo;
    float4 f = *(const float4*)(src + off);
    uint2 o;
    o.x = packbf2(f.x, f.y);
    o.y = packbf2(f.z, f.w);
    *(uint2*)(dst + (size_t)mat * CC * CC + off) = o;
}

// ---------------------------------------------------------------------------
// GroupNorm pass 1 (stats)
// ---------------------------------------------------------------------------
__global__ void gn_stats(const float* __restrict__ x, float2* __restrict__ stats) {
    const int bg = blockIdx.x;
    const int b  = bg / NGROUPS;
    const int g  = bg % NGROUPS;
    const size_t base = ((size_t)b * CC + (size_t)g * CPG) * LL;
    const float* xp = x + base;

    float s = 0.f, s2 = 0.f;
    for (int i = threadIdx.x; i < GROUP_ELEMS; i += blockDim.x) {
        float v = xp[i];
        s += v; s2 += v * v;
    }
    __shared__ float red1[16], red2[16];
    s = warp_sum(s); s2 = warp_sum(s2);
    const int lane = threadIdx.x & 31, wid = threadIdx.x >> 5;
    if (lane == 0) { red1[wid] = s; red2[wid] = s2; }
    __syncthreads();
    if (threadIdx.x == 0) {
        float t = 0.f, t2 = 0.f;
        #pragma unroll
        for (int i = 0; i < 16; i++) { t += red1[i]; t2 += red2[i]; }
        float mean = t * (1.0f / GROUP_ELEMS);
        float var  = t2 * (1.0f / GROUP_ELEMS) - mean * mean;
        stats[bg] = make_float2(mean, rsqrtf(var + EPS));
    }
}

// ---------------------------------------------------------------------------
// GroupNorm pass 2: normalize + transpose + bf16 -> hT[b][l][c]
// ---------------------------------------------------------------------------
__global__ void gn_norm_t(const float* __restrict__ x,
                          const float2* __restrict__ stats,
                          const float* __restrict__ gamma,
                          const float* __restrict__ beta,
                          __nv_bfloat16* __restrict__ hT) {
    const int b = blockIdx.z;
    const int l0 = blockIdx.x * 32;
    const int c0 = blockIdx.y * 64;
    const int tx = threadIdx.x & 31, ty = threadIdx.x >> 5;
    __shared__ float tile[64][33];

    const float* xb = x + (size_t)b * CC * LL;
    #pragma unroll
    for (int i = 0; i < 8; i++) {
        int c = c0 + i * 8 + ty;
        float2 st = stats[b * NGROUPS + (c >> 4)];
        float gm = gamma[c], bt = beta[c];
        float xv = xb[(size_t)c * LL + l0 + tx];
        tile[c - c0][tx] = (xv - st.x) * st.y * gm + bt;
    }
    __syncthreads();
    __nv_bfloat16* ht = hT + (size_t)b * LL * CC;
    #pragma unroll
    for (int i = 0; i < 4; i++) {
        int l = i * 8 + ty;
        __nv_bfloat162 o;
        o.x = __float2bfloat16_rn(tile[tx * 2][l]);
        o.y = __float2bfloat16_rn(tile[tx * 2 + 1][l]);
        *(__nv_bfloat162*)(ht + (size_t)(l0 + l) * CC + c0 + tx * 2) = o;
    }
}

// ---------------------------------------------------------------------------
// R10 GEMM engine, pure-bf16 operands (all cp.async).  4 warps (2x2),
// CTA tile 128x128 x BK=64, warp tile 64x64, 2-stage, 2 CTAs/SM.
//   out[m,n] = sum_k A[m,k] * B[n,k]  (+ epilogue)
// EPI: 1 +bias[m] ; 2 +bias[m]+X, fp32 out ; 3 exp(v*scale) + rowsum partials
//      4 +bias[n] ; 5 * (1/rowsum[m]) reduced inline from aux partials
// ---------------------------------------------------------------------------
#define BKK 64
#define SROW 72        // 64 + 8 pad (144B rows: 16B aligned, ldmatrix conflict-free)
#define STG_ELEM (128 * SROW)
#define SM_TOTAL (4 * STG_ELEM * 2)   // 2 stages x (A+B) bf16 = 73728 B

template<int EPI, bool OUT_BF16>
__device__ __forceinline__
void gemm_body(__nv_bfloat16* smem, int bx, int by, int z,
               const __nv_bfloat16* __restrict__ Ag, int lda, size_t strA,
               const __nv_bfloat16* __restrict__ Bg, int ldb, size_t strB,
               void* __restrict__ Og, int ldo, size_t strO,
               int K, const float* __restrict__ bias,
               const float* __restrict__ X, size_t strX,
               float scale, float* __restrict__ aux) {
    __nv_bfloat16* smA = smem;                 // 2 stages
    __nv_bfloat16* smB = smem + 2 * STG_ELEM;  // 2 stages

    const int tid = threadIdx.x, lane = tid & 31, warp = tid >> 5;   // warp 0..3
    const int wm = warp >> 1, wn = warp & 1;                          // 2x2
    const int g = lane >> 2, tig = lane & 3;
    const int mBase = by * 128, nBase = bx * 128;

    const int nk = K / BKK;

    auto issue_stage = [&](int kt) {
        if (kt < nk) {
            const int buf = kt & 1;
            const int k0 = kt * BKK;
            __nv_bfloat16* sA = smA + buf * STG_ELEM;
            __nv_bfloat16* sB = smB + buf * STG_ELEM;
            #pragma unroll
            for (int it = 0; it < 8; it++) {
                const int s = tid + it * 128;
                const int row = s >> 3;
                const int col8 = (s & 7) * 8;
                cp16(sA + row * SROW + col8,
                     Ag + strA * z + (size_t)(mBase + row) * lda + k0 + col8);
                cp16(sB + row * SROW + col8,
                     Bg + strB * z + (size_t)(nBase + row) * ldb + k0 + col8);
            }
        }
        cp_commit();
    };

    float acc[4][8][4];
    #pragma unroll
    for (int i = 0; i < 4; i++)
        #pragma unroll
        for (int j = 0; j < 8; j++)
            #pragma unroll
            for (int r = 0; r < 4; r++) acc[i][j][r] = 0.f;

    issue_stage(0);
    issue_stage(1);

    for (int kt = 0; kt < nk; kt++) {
        const int buf = kt & 1;
        const __nv_bfloat16* sA = smA + buf * STG_ELEM;
        const __nv_bfloat16* sB = smB + buf * STG_ELEM;

        cp_wait1();            // stage kt resident
        __syncthreads();

        #pragma unroll
        for (int ks = 0; ks < 4; ks++) {
            uint32_t af[4][4], bf[8][2];
            #pragma unroll
            for (int mt = 0; mt < 4; mt++) {
                const __nv_bfloat16* p = &sA[(wm * 64 + mt * 16 + (lane & 15)) * SROW
                                             + ks * 16 + ((lane >> 4) << 3)];
                ldsm4(af[mt], p);
            }
            #pragma unroll
            for (int np = 0; np < 4; np++) {
                const __nv_bfloat16* p = &sB[(wn * 64 + np * 16 + (lane & 7) + ((lane >> 4) << 3)) * SROW
                                             + ks * 16 + (((lane >> 3) & 1) << 3)];
                uint32_t t[4];
                ldsm4(t, p);
                bf[np * 2][0] = t[0]; bf[np * 2][1] = t[1];
                bf[np * 2 + 1][0] = t[2]; bf[np * 2 + 1][1] = t[3];
            }
            #pragma unroll
            for (int mt = 0; mt < 4; mt++)
                #pragma unroll
                for (int nt = 0; nt < 8; nt++)
                    mma16(acc[mt][nt], af[mt], bf[nt]);
        }

        __syncthreads();       // all warps finished reading buf
        issue_stage(kt + 2);   // refill it
    }

    // ---- epilogue ----
    float bn0[8], bn1[8];
    if (EPI == 4) {
        #pragma unroll
        for (int nt = 0; nt < 8; nt++) {
            int col = nBase + wn * 64 + nt * 8 + tig * 2;
            bn0[nt] = bias[col]; bn1[nt] = bias[col + 1];
        }
    }
    #pragma unroll
    for (int mt = 0; mt < 4; mt++) {
        #pragma unroll
        for (int half = 0; half < 2; half++) {
            const int row = mBase + wm * 64 + mt * 16 + g + half * 8;
            float bm = (EPI == 1 || EPI == 2) ? bias[row] : 0.f;
            float rsmul = 0.f;
            if (EPI == 5) {
                const float* pp = aux + ((size_t)z * LL + row) * 32 + tig * 8;
                float s0 = (pp[0] + pp[1]) + (pp[2] + pp[3]);
                float s1 = (pp[4] + pp[5]) + (pp[6] + pp[7]);
                float s = s0 + s1;
                s += __shfl_xor_sync(0xffffffffu, s, 1);
                s += __shfl_xor_sync(0xffffffffu, s, 2);
                rsmul = 1.0f / s;
            }
            float rsum = 0.f;
            #pragma unroll
            for (int nt = 0; nt < 8; nt++) {
                const int col = nBase + wn * 64 + nt * 8 + tig * 2;
                float v0 = acc[mt][nt][half * 2 + 0];
                float v1 = acc[mt][nt][half * 2 + 1];
                if (EPI == 1 || EPI == 2) { v0 += bm; v1 += bm; }
                if (EPI == 4) { v0 += bn0[nt]; v1 += bn1[nt]; }
                if (EPI == 5) { v0 *= rsmul; v1 *= rsmul; }
                if (EPI == 2) {
                    const float* xr = X + strX * z + (size_t)row * ldo + col;
                    v0 += xr[0]; v1 += xr[1];
                }
                if (EPI == 3) {
                    v0 = __expf(v0 * scale);
                    v1 = __expf(v1 * scale);
                    __nv_bfloat162 st = __floats2bfloat162_rn(v0, v1);
                    *(__nv_bfloat162*)((__nv_bfloat16*)Og + strO * z
                                       + (size_t)row * ldo + col) = st;
                    rsum += __bfloat162float(st.x) + __bfloat162float(st.y);
                } else if constexpr (OUT_BF16) {
                    __nv_bfloat162 st = __floats2bfloat162_rn(v0, v1);
                    *(__nv_bfloat162*)((__nv_bfloat16*)Og + strO * z
                                       + (size_t)row * ldo + col) = st;
                } else {
                    float2 st = { v0, v1 };
                    *(float2*)((float*)Og + strO * z + (size_t)row * ldo + col) = st;
                }
            }
            if (EPI == 3) {
                rsum += __shfl_xor_sync(0xffffffffu, rsum, 1);
                rsum += __shfl_xor_sync(0xffffffffu, rsum, 2);
                if (tig == 0)
                    aux[((size_t)z * LL + row) * 32 + bx * 2 + wn] = rsum;
            }
        }
    }
}

// ---------------------------------------------------------------------------
// Kernel wrappers
// ---------------------------------------------------------------------------
template<int EPI, bool OUT_BF16>
__global__ __launch_bounds__(128, 2)
void gemm_k(const __nv_bfloat16* __restrict__ Ag, int lda, size_t strA,
            const __nv_bfloat16* __restrict__ Bg, int ldb, size_t strB,
            void* __restrict__ Og, int ldo, size_t strO,
            int K, const float* __restrict__ bias,
            const float* __restrict__ X, size_t strX,
            float scale, float* __restrict__ aux) {
    extern __shared__ __align__(16) __nv_bfloat16 smem[];
    gemm_body<EPI, OUT_BF16>(
        smem, blockIdx.x, blockIdx.y, blockIdx.z,
        Ag, lda, strA, Bg, ldb, strB, Og, ldo, strO,
        K, bias, X, strX, scale, aux);
}

// Merged q/k/V projections in one 1D launch (all-bf16 weights).
//  blocks [0, 1024):  qk — bx=bid&3, by=(bid>>2)&15, zz=bid>>6 (0..15)
//  blocks [1024, 1536): V — t=bid-1024: bx=t&15, by=(t>>4)&3, z=t>>6
#define QK_BLOCKS 1024
#define QKV_BLOCKS 1536

__global__ __launch_bounds__(128, 2)
void qkv_k(const __nv_bfloat16* __restrict__ hT,
           const __nv_bfloat16* __restrict__ Wbf,
           const float* __restrict__ bq, __nv_bfloat16* __restrict__ qT,
           const float* __restrict__ bk, __nv_bfloat16* __restrict__ kT,
           const float* __restrict__ bv, __nv_bfloat16* __restrict__ v) {
    extern __shared__ __align__(16) __nv_bfloat16 smem[];
    const size_t CL = (size_t)CC * LL;
    const size_t WSZ = (size_t)CC * CC;
    const int bid = blockIdx.x;
    if (bid < QK_BLOCKS) {
        const int bx = bid & 3;
        const int by = (bid >> 2) & 15;
        const int zz = bid >> 6;
        const __nv_bfloat16* W = (zz < 8) ? Wbf : Wbf + WSZ;
        const float* b = (zz < 8) ? bq : bk;
        __nv_bfloat16* O = (zz < 8) ? qT : kT;
        const int z = (zz < 8) ? zz : zz - 8;
        // qT/kT[l][o] = hT @ W^T + b[n]   (M=L, N=C, K=C)
        gemm_body<4, true>(
            smem, bx, by, z,
            hT, CC, CL, W, CC, 0, O, CC, CL, CC, b, nullptr, 0, 0.f, nullptr);
    } else {
        const int t = bid - QK_BLOCKS;
        const int bx = t & 15;
        const int by = (t >> 4) & 3;
        const int z = t >> 6;
        // v[c][l] = Wv @ h + bv[m]   (M=C, N=L, K=C)
        gemm_body<1, true>(
            smem, bx, by, z,
            Wbf + 2 * WSZ, CC, 0, hT, CC, CL, v, LL, CL, CC, bv,
            nullptr, 0, 0.f, nullptr);
    }
}

// ---------------------------------------------------------------------------
// Launch
// ---------------------------------------------------------------------------
extern "C" void kernel_launch(void* const* d_in, const int* in_sizes, int n_in,
                              void* d_out, int out_size) {
    const float* x        = (const float*)d_in[0];
    const float* gn_gamma = (const float*)d_in[1];
    const float* gn_beta  = (const float*)d_in[2];
    const float* Wq = (const float*)d_in[3];
    const float* bq = (const float*)d_in[4];
    const float* Wk = (const float*)d_in[5];
    const float* bk = (const float*)d_in[6];
    const float* Wv = (const float*)d_in[7];
    const float* bv = (const float*)d_in[8];
    const float* Wo = (const float*)d_in[9];
    const float* bo = (const float*)d_in[10];
    float* out = (float*)d_out;

    __nv_bfloat16 *hT, *qT, *kT, *v, *aT, *e, *Wbf;
    float *part; float2* stats;
    cudaGetSymbolAddress((void**)&hT, g_hT);
    cudaGetSymbolAddress((void**)&qT, g_qT);
    cudaGetSymbolAddress((void**)&kT, g_kT);
    cudaGetSymbolAddress((void**)&v,  g_v);
    cudaGetSymbolAddress((void**)&aT, g_aT);
    cudaGetSymbolAddress((void**)&e,  g_e);
    cudaGetSymbolAddress((void**)&part, g_part);
    cudaGetSymbolAddress((void**)&stats, g_stats);
    cudaGetSymbolAddress((void**)&Wbf, g_Wbf);

    const size_t CL  = (size_t)CC * LL;
    const size_t LLs = (size_t)LL * LL;
    const size_t WSZ = (size_t)CC * CC;
    const float scale = 0.044194173824159216f;   // 1/sqrt(512)

    cudaFuncSetAttribute(qkv_k,
                         cudaFuncAttributeMaxDynamicSharedMemorySize, SM_TOTAL);
    cudaFuncSetAttribute(gemm_k<3, true>,
                         cudaFuncAttributeMaxDynamicSharedMemorySize, SM_TOTAL);
    cudaFuncSetAttribute(gemm_k<5, true>,
                         cudaFuncAttributeMaxDynamicSharedMemorySize, SM_TOTAL);
    cudaFuncSetAttribute(gemm_k<2, false>,
                         cudaFuncAttributeMaxDynamicSharedMemorySize, SM_TOTAL);

    // 0. weight conversion fp32 -> bf16 (once per launch; tiny)
    conv_w<<<1024, 256>>>(Wq, Wk, Wv, Wo, Wbf);

    // 1. GroupNorm
    gn_stats<<<BATCH * NGROUPS, 512>>>(x, stats);
    gn_norm_t<<<dim3(LL / 32, CC / 64, BATCH), 256>>>(x, stats, gn_gamma, gn_beta, hT);

    // 2. merged q/k/V projections (one 1D launch, 1536 blocks, all bf16)
    qkv_k<<<QKV_BLOCKS, 128, SM_TOTAL>>>(hT, Wbf, bq, qT, bk, kT, bv, v);

    // 3. e[i][j] = exp(scale * qT@kT^T), + rowsum partials  (M=N=L, K=C)
    dim3 gS(LL / 128, LL / 128, BATCH);
    gemm_k<3, true><<<gS, 128, SM_TOTAL>>>(
        qT, CC, CL, kT, CC, CL, e, LL, LLs, CC, nullptr, nullptr, 0, scale, part);

    // 4. aT[i][c] = (e @ v^T) * (1/rowsum[i], reduced inline)  (M=L, N=C, K=L)
    dim3 gT(CC / 128, LL / 128, BATCH);
    gemm_k<5, true><<<gT, 128, SM_TOTAL>>>(
        e, LL, LLs, v, LL, CL, aT, CC, CL, LL, nullptr, nullptr, 0, 0.f, part);

    // 5. out[o][l] = x + Wo @ aT^T + bo   (M=C, N=L, K=C)
    dim3 gV(LL / 128, CC / 128, BATCH);
    gemm_k<2, false><<<gV, 128, SM_TOTAL>>>(
        Wbf + 3 * WSZ, CC, 0, aT, CC, CL, out, LL, CL, CC, bo, x, CL, 0.f, part);
}